// round 4
// baseline (speedup 1.0000x reference)
#include <cuda_runtime.h>

// DQSN: spiking MLP collapsed to 2 GEMMs (T=16 timesteps folded analytically).
//   s[b,h]  = IFsim(x @ w1^T + b1)          (16-step IF neuron -> weighted spike sum,
//                                            weight 2^(t-16) from LIF linearity)
//   out     = s @ w2^T + (1 - 2^-16) * b2   (closed-form LIF readout)
//
// B=8192, I=256, H=1024, O=256.
// GEMM core: double-buffered smem, fp32x2 packed FMA (Blackwell FFMA2 via
// PTX fma.rn.f32x2). Row-pair accumulators so the A operand is a native
// 64-bit smem word (no packing MOVs for A; only 8 (b,b) packs per k).

namespace {

constexpr int BN = 128;
constexpr int BK = 16;

// Scratch for the weighted-spike matrix s (8192 x 1024 fp32 = 32 MB).
__device__ float g_s[8192u * 1024u];

using u64 = unsigned long long;

__device__ __forceinline__ u64 pack2(float lo, float hi) {
    u64 r;
    asm("mov.b64 %0, {%1, %2};" : "=l"(r) : "f"(lo), "f"(hi));
    return r;
}
__device__ __forceinline__ void unpack2(u64 d, float& lo, float& hi) {
    asm("mov.b64 {%0, %1}, %2;" : "=f"(lo), "=f"(hi) : "l"(d));
}
__device__ __forceinline__ void ffma2(u64& d, u64 a, u64 b) {
    // d.lo += a.lo*b.lo ; d.hi += a.hi*b.hi   (each lane rn fp32 FMA)
    asm("fma.rn.f32x2 %0, %1, %2, %0;" : "+l"(d) : "l"(a), "l"(b));
}

// MODE 0: C = IFsim(A@B^T + bias) -> g_s   (Cout ignored)
// MODE 1: A = g_s (Ain ignored),  C = A@B^T + (1-2^-16)*bias
// BM = 128 (4 row-pairs/thread) or 64 (2 row-pairs/thread). BN fixed at 128.
template <int MODE, int BM>
__global__ void __launch_bounds__(256, 2)
sgemm_nt_fused(const float* __restrict__ Ain, const float* __restrict__ Bmat,
               const float* __restrict__ bias, float* __restrict__ Cout,
               int M, int N, int K)
{
    constexpr int RP = BM / 32;   // row-pairs per thread: 4 or 2
    constexpr int NA = BM / 64;   // float4 A-loads per thread per tile: 2 or 1

    // 16B alignment is REQUIRED: inner loop uses LDS.128 via float4/ulonglong2
    // casts; row stride (BM+4)*4B and (BN+4)*4B are multiples of 16B.
    __shared__ __align__(16) float As[2][BK][BM + 4];
    __shared__ __align__(16) float Bs[2][BK][BN + 4];

    const float* A = (MODE == 1) ? (const float*)g_s : Ain;
    float*       C = (MODE == 0) ? (float*)g_s       : Cout;

    const int tx = threadIdx.x;          // 0..15
    const int ty = threadIdx.y;          // 0..15
    const int tid = ty * 16 + tx;        // 0..255
    const int mBase = blockIdx.y * BM;
    const int nBase = blockIdx.x * BN;

    const int ldRow = tid >> 2;          // 0..63
    const int ldK   = (tid & 3) * 4;     // 0,4,8,12

    const int nk = K / BK;

    // Per-thread base pointers for tile loads (hoisted addressing).
    const float* aPtr = A    + (size_t)(mBase + ldRow) * K + ldK;
    const float* bPtr = Bmat + (size_t)(nBase + ldRow) * K + ldK;

    // ---- prologue: load tile 0 into stage 0 ----
    #pragma unroll
    for (int l = 0; l < NA; l++) {
        const int row = ldRow + 64 * l;
        float4 va = *(const float4*)(aPtr + (size_t)(64 * l) * K);
        As[0][ldK + 0][row] = va.x;
        As[0][ldK + 1][row] = va.y;
        As[0][ldK + 2][row] = va.z;
        As[0][ldK + 3][row] = va.w;
    }
    #pragma unroll
    for (int l = 0; l < 2; l++) {
        const int row = ldRow + 64 * l;
        float4 vb = *(const float4*)(bPtr + (size_t)(64 * l) * K);
        Bs[0][ldK + 0][row] = vb.x;
        Bs[0][ldK + 1][row] = vb.y;
        Bs[0][ldK + 2][row] = vb.z;
        Bs[0][ldK + 3][row] = vb.w;
    }
    __syncthreads();

    // acc2[ip][j]: lo lane = local row pair base, hi lane = +1 (see epilogue)
    u64 acc2[RP][8];
    #pragma unroll
    for (int i = 0; i < RP; i++)
        #pragma unroll
        for (int j = 0; j < 8; j++) acc2[i][j] = 0ull;

    for (int kt = 0; kt < nk; kt++) {
        const int cur = kt & 1;
        const int nxt = cur ^ 1;

        // ---- prefetch next tile into registers ----
        float4 ra[NA], rb[2];
        const bool more = (kt + 1) < nk;
        if (more) {
            const int kOff = (kt + 1) * BK;
            #pragma unroll
            for (int l = 0; l < NA; l++)
                ra[l] = *(const float4*)(aPtr + (size_t)(64 * l) * K + kOff);
            #pragma unroll
            for (int l = 0; l < 2; l++)
                rb[l] = *(const float4*)(bPtr + (size_t)(64 * l) * K + kOff);
        }

        // ---- compute on current stage ----
        #pragma unroll
        for (int k = 0; k < BK; k++) {
            // A row-pairs read directly as 64-bit words (no packing MOVs)
            u64 ap[RP];
            {
                ulonglong2 a01 = *(const ulonglong2*)&As[cur][k][ty * 4];
                ap[0] = a01.x;  // rows (ty*4+0, ty*4+1)
                ap[1] = a01.y;  // rows (ty*4+2, ty*4+3)
                if (RP == 4) {
                    ulonglong2 a23 = *(const ulonglong2*)&As[cur][k][64 + ty * 4];
                    ap[2] = a23.x;
                    ap[3] = a23.y;
                }
            }
            float4 b0 = *(const float4*)&Bs[cur][k][tx * 4];
            float4 b1 = *(const float4*)&Bs[cur][k][64 + tx * 4];
            u64 bp[8] = {
                pack2(b0.x, b0.x), pack2(b0.y, b0.y),
                pack2(b0.z, b0.z), pack2(b0.w, b0.w),
                pack2(b1.x, b1.x), pack2(b1.y, b1.y),
                pack2(b1.z, b1.z), pack2(b1.w, b1.w)
            };
            #pragma unroll
            for (int ip = 0; ip < RP; ip++)
                #pragma unroll
                for (int j = 0; j < 8; j++)
                    ffma2(acc2[ip][j], ap[ip], bp[j]);
        }

        // ---- store prefetched tile into next stage ----
        if (more) {
            #pragma unroll
            for (int l = 0; l < NA; l++) {
                const int row = ldRow + 64 * l;
                As[nxt][ldK + 0][row] = ra[l].x;
                As[nxt][ldK + 1][row] = ra[l].y;
                As[nxt][ldK + 2][row] = ra[l].z;
                As[nxt][ldK + 3][row] = ra[l].w;
            }
            #pragma unroll
            for (int l = 0; l < 2; l++) {
                const int row = ldRow + 64 * l;
                Bs[nxt][ldK + 0][row] = rb[l].x;
                Bs[nxt][ldK + 1][row] = rb[l].y;
                Bs[nxt][ldK + 2][row] = rb[l].z;
                Bs[nxt][ldK + 3][row] = rb[l].w;
            }
            __syncthreads();
        }
    }

    // ---- epilogue ----
    float bcol[8];
    #pragma unroll
    for (int j = 0; j < 8; j++) {
        const int col = nBase + ((j < 4) ? (tx * 4 + j) : (64 + tx * 4 + (j - 4)));
        bcol[j] = bias[col];
    }

    #pragma unroll
    for (int ip = 0; ip < RP; ip++) {
        // lo lane -> row rl, hi lane -> row rl+1
        const int rl = (ip < 2) ? (ty * 4 + 2 * ip) : (64 + ty * 4 + 2 * (ip - 2));
        float lov[8], hiv[8];
        #pragma unroll
        for (int j = 0; j < 8; j++) unpack2(acc2[ip][j], lov[j], hiv[j]);

        #pragma unroll
        for (int half = 0; half < 2; half++) {
            const float* vals = half ? hiv : lov;
            const int row = mBase + rl + half;
            float4 outv[2];
            #pragma unroll
            for (int j = 0; j < 8; j++) {
                float r;
                if (MODE == 0) {
                    // IF neuron (hard reset), T=16; LIF weight for step t is 2^(t-16).
                    const float h = vals[j] + bcol[j];
                    float v = 0.f, s = 0.f, wt = 1.f / 65536.f;
                    #pragma unroll
                    for (int t = 0; t < 16; t++) {
                        v += h;
                        if (v >= 1.f) { s += wt; v = 0.f; }
                        wt *= 2.f;
                    }
                    r = s;
                } else {
                    // (1 - 2^-16) * b2  (geometric sum of LIF decay weights)
                    r = vals[j] + bcol[j] * 0.9999847412109375f;
                }
                ((float*)outv)[j] = r;
            }
            *(float4*)&C[(size_t)row * N + nBase + tx * 4]      = outv[0];
            *(float4*)&C[(size_t)row * N + nBase + 64 + tx * 4] = outv[1];
        }
    }
}

} // anonymous namespace

extern "C" void kernel_launch(void* const* d_in, const int* in_sizes, int n_in,
                              void* d_out, int out_size)
{
    const float* x  = (const float*)d_in[0];  // [8192, 256]
    const float* w1 = (const float*)d_in[1];  // [1024, 256]
    const float* b1 = (const float*)d_in[2];  // [1024]
    const float* w2 = (const float*)d_in[3];  // [256, 1024]
    const float* b2 = (const float*)d_in[4];  // [256]
    float* out = (float*)d_out;               // [8192, 256]

    const int B = 8192, I = 256, H = 1024, O = 256;

    dim3 block(16, 16);

    // GEMM1 (128x128 tiles) + fused IF simulation -> g_s [B, H]
    dim3 grid1(H / BN, B / 128);  // (8, 64) = 512 CTAs
    sgemm_nt_fused<0, 128><<<grid1, block>>>(x, w1, b1, nullptr, B, H, I);

    // GEMM2 (64x128 tiles): out = g_s @ w2^T + (1-2^-16)*b2
    dim3 grid2(O / BN, B / 64);   // (2, 128) = 256 CTAs
    sgemm_nt_fused<1, 64><<<grid2, block>>>(nullptr, w2, b2, out, B, O, H);

    (void)in_sizes; (void)n_in; (void)out_size;
}

// round 12
// speedup vs baseline: 1.0494x; 1.0494x over previous
#include <cuda_runtime.h>

// DQSN: spiking MLP collapsed to 2 GEMMs (T=16 timesteps folded analytically).
//   s[b,h]  = IFsim(x @ w1^T + b1)          (16-step IF neuron -> weighted spike sum,
//                                            weight 2^(t-16) from LIF linearity)
//   out     = s @ w2^T + (1 - 2^-16) * b2   (closed-form LIF readout)
//
// B=8192, I=256, H=1024, O=256.
// NOTE: harness compiles via compute_103 PTX (no 'a' feature target) -> tcgen05
// is unavailable. FFMA2 (fma.rn.f32x2) is the peak-rate primitive here.
// GEMM core: double-buffered smem, fp32x2 packed FMA, row-pair accumulators
// (A operand = native 64-bit smem word; only BN/16 (b,b) packing MOVs per k).
// GEMM2 retiled BM=128 x BN=64 (8 rows x 4 cols/thread): FFMA2-per-crossbar-
// wavefront ratio = 2*RP doubles vs the measured 77%-L1-bound BM=64 config.

namespace {

constexpr int BK = 16;

// Scratch for the weighted-spike matrix s (8192 x 1024 fp32 = 32 MB).
__device__ __align__(128) float g_s[8192u * 1024u];

using u64 = unsigned long long;

__device__ __forceinline__ u64 pack2(float lo, float hi) {
    u64 r;
    asm("mov.b64 %0, {%1, %2};" : "=l"(r) : "f"(lo), "f"(hi));
    return r;
}
__device__ __forceinline__ void unpack2(u64 d, float& lo, float& hi) {
    asm("mov.b64 {%0, %1}, %2;" : "=f"(lo), "=f"(hi) : "l"(d));
}
__device__ __forceinline__ void ffma2(u64& d, u64 a, u64 b) {
    // d.lo += a.lo*b.lo ; d.hi += a.hi*b.hi   (each lane rn fp32 FMA)
    asm("fma.rn.f32x2 %0, %1, %2, %0;" : "+l"(d) : "l"(a), "l"(b));
}

// MODE 0: C = IFsim(A@B^T + bias) -> g_s   (Cout ignored)
// MODE 1: A = g_s (Ain ignored),  C = A@B^T + (1-2^-16)*bias
// BM = 128: 4 row-pairs/thread. BN in {64,128}: 4 or 8 cols/thread.
template <int MODE, int BM, int BN>
__global__ void __launch_bounds__(256, 2)
sgemm_nt_fused(const float* __restrict__ Ain, const float* __restrict__ Bmat,
               const float* __restrict__ bias, float* __restrict__ Cout,
               int M, int N, int K)
{
    constexpr int RP = BM / 32;   // row-pairs per thread (4 for BM=128)
    constexpr int NA = BM / 64;   // float4 A-loads per thread per tile
    constexpr int NB = BN / 64;   // float4 B-loads per thread per tile
    constexpr int JC = BN / 16;   // cols per thread (8 or 4)

    // 16B alignment REQUIRED: inner loop uses LDS.128 via float4/ulonglong2
    // casts; row strides (BM+4)*4B, (BN+4)*4B are multiples of 16B.
    __shared__ __align__(16) float As[2][BK][BM + 4];
    __shared__ __align__(16) float Bs[2][BK][BN + 4];

    const float* A = (MODE == 1) ? (const float*)g_s : Ain;
    float*       C = (MODE == 0) ? (float*)g_s       : Cout;

    const int tx = threadIdx.x;          // 0..15
    const int ty = threadIdx.y;          // 0..15
    const int tid = ty * 16 + tx;        // 0..255
    const int mBase = blockIdx.y * BM;
    const int nBase = blockIdx.x * BN;

    const int ldRow = tid >> 2;          // 0..63
    const int ldK   = (tid & 3) * 4;     // 0,4,8,12

    const int nk = K / BK;

    // Per-thread base pointers for tile loads (hoisted addressing).
    const float* aPtr = A    + (size_t)(mBase + ldRow) * K + ldK;
    const float* bPtr = Bmat + (size_t)(nBase + ldRow) * K + ldK;

    // ---- prologue: load tile 0 into stage 0 ----
    #pragma unroll
    for (int l = 0; l < NA; l++) {
        const int row = ldRow + 64 * l;
        float4 va = *(const float4*)(aPtr + (size_t)(64 * l) * K);
        As[0][ldK + 0][row] = va.x;
        As[0][ldK + 1][row] = va.y;
        As[0][ldK + 2][row] = va.z;
        As[0][ldK + 3][row] = va.w;
    }
    #pragma unroll
    for (int l = 0; l < NB; l++) {
        const int row = ldRow + 64 * l;
        float4 vb = *(const float4*)(bPtr + (size_t)(64 * l) * K);
        Bs[0][ldK + 0][row] = vb.x;
        Bs[0][ldK + 1][row] = vb.y;
        Bs[0][ldK + 2][row] = vb.z;
        Bs[0][ldK + 3][row] = vb.w;
    }
    __syncthreads();

    // acc2[ip][j]: lo lane = local row pair base, hi lane = +1 (see epilogue)
    u64 acc2[RP][JC];
    #pragma unroll
    for (int i = 0; i < RP; i++)
        #pragma unroll
        for (int j = 0; j < JC; j++) acc2[i][j] = 0ull;

    for (int kt = 0; kt < nk; kt++) {
        const int cur = kt & 1;
        const int nxt = cur ^ 1;

        // ---- prefetch next tile into registers ----
        float4 ra[NA], rb[NB];
        const bool more = (kt + 1) < nk;
        if (more) {
            const int kOff = (kt + 1) * BK;
            #pragma unroll
            for (int l = 0; l < NA; l++)
                ra[l] = *(const float4*)(aPtr + (size_t)(64 * l) * K + kOff);
            #pragma unroll
            for (int l = 0; l < NB; l++)
                rb[l] = *(const float4*)(bPtr + (size_t)(64 * l) * K + kOff);
        }

        // ---- compute on current stage ----
        #pragma unroll
        for (int k = 0; k < BK; k++) {
            // A row-pairs read directly as 64-bit words (no packing MOVs)
            u64 ap[RP];
            {
                ulonglong2 a01 = *(const ulonglong2*)&As[cur][k][ty * 4];
                ap[0] = a01.x;  // rows (ty*4+0, ty*4+1)
                ap[1] = a01.y;  // rows (ty*4+2, ty*4+3)
                if (RP == 4) {
                    ulonglong2 a23 = *(const ulonglong2*)&As[cur][k][64 + ty * 4];
                    ap[2] = a23.x;
                    ap[3] = a23.y;
                }
            }
            u64 bp[JC];
            {
                float4 b0 = *(const float4*)&Bs[cur][k][tx * 4];
                bp[0] = pack2(b0.x, b0.x); bp[1] = pack2(b0.y, b0.y);
                bp[2] = pack2(b0.z, b0.z); bp[3] = pack2(b0.w, b0.w);
                if (JC == 8) {
                    float4 b1 = *(const float4*)&Bs[cur][k][64 + tx * 4];
                    bp[4] = pack2(b1.x, b1.x); bp[5] = pack2(b1.y, b1.y);
                    bp[6] = pack2(b1.z, b1.z); bp[7] = pack2(b1.w, b1.w);
                }
            }
            #pragma unroll
            for (int ip = 0; ip < RP; ip++)
                #pragma unroll
                for (int j = 0; j < JC; j++)
                    ffma2(acc2[ip][j], ap[ip], bp[j]);
        }

        // ---- store prefetched tile into next stage ----
        if (more) {
            #pragma unroll
            for (int l = 0; l < NA; l++) {
                const int row = ldRow + 64 * l;
                As[nxt][ldK + 0][row] = ra[l].x;
                As[nxt][ldK + 1][row] = ra[l].y;
                As[nxt][ldK + 2][row] = ra[l].z;
                As[nxt][ldK + 3][row] = ra[l].w;
            }
            #pragma unroll
            for (int l = 0; l < NB; l++) {
                const int row = ldRow + 64 * l;
                Bs[nxt][ldK + 0][row] = rb[l].x;
                Bs[nxt][ldK + 1][row] = rb[l].y;
                Bs[nxt][ldK + 2][row] = rb[l].z;
                Bs[nxt][ldK + 3][row] = rb[l].w;
            }
            __syncthreads();
        }
    }

    // ---- epilogue ----
    float bcol[JC];
    #pragma unroll
    for (int j = 0; j < JC; j++) {
        const int col = nBase + ((j < 4) ? (tx * 4 + j) : (64 + tx * 4 + (j - 4)));
        bcol[j] = bias[col];
    }

    #pragma unroll
    for (int ip = 0; ip < RP; ip++) {
        // lo lane -> row rl, hi lane -> row rl+1
        const int rl = (ip < 2) ? (ty * 4 + 2 * ip) : (64 + ty * 4 + 2 * (ip - 2));
        float lov[JC], hiv[JC];
        #pragma unroll
        for (int j = 0; j < JC; j++) unpack2(acc2[ip][j], lov[j], hiv[j]);

        #pragma unroll
        for (int half = 0; half < 2; half++) {
            const float* vals = half ? hiv : lov;
            const int row = mBase + rl + half;
            float4 outv[JC / 4];
            #pragma unroll
            for (int j = 0; j < JC; j++) {
                float r;
                if (MODE == 0) {
                    // IF neuron (hard reset), T=16; LIF weight for step t is 2^(t-16).
                    const float h = vals[j] + bcol[j];
                    float v = 0.f, s = 0.f, wt = 1.f / 65536.f;
                    #pragma unroll
                    for (int t = 0; t < 16; t++) {
                        v += h;
                        if (v >= 1.f) { s += wt; v = 0.f; }
                        wt *= 2.f;
                    }
                    r = s;
                } else {
                    // (1 - 2^-16) * b2  (geometric sum of LIF decay weights)
                    r = vals[j] + bcol[j] * 0.9999847412109375f;
                }
                ((float*)outv)[j] = r;
            }
            *(float4*)&C[(size_t)row * N + nBase + tx * 4] = outv[0];
            if (JC == 8)
                *(float4*)&C[(size_t)row * N + nBase + 64 + tx * 4] = outv[1];
        }
    }
}

} // anonymous namespace

extern "C" void kernel_launch(void* const* d_in, const int* in_sizes, int n_in,
                              void* d_out, int out_size)
{
    const float* x  = (const float*)d_in[0];  // [8192, 256]
    const float* w1 = (const float*)d_in[1];  // [1024, 256]
    const float* b1 = (const float*)d_in[2];  // [1024]
    const float* w2 = (const float*)d_in[3];  // [256, 1024]
    const float* b2 = (const float*)d_in[4];  // [256]
    float* out = (float*)d_out;               // [8192, 256]

    const int B = 8192, I = 256, H = 1024, O = 256;

    dim3 block(16, 16);

    // GEMM1 (128x128 tiles, bit-identical to the 217.6us PASS) -> g_s [B, H]
    dim3 grid1(H / 128, B / 128);  // (8, 64) = 512 CTAs
    sgemm_nt_fused<0, 128, 128><<<grid1, block>>>(x, w1, b1, nullptr, B, H, I);

    // GEMM2 (128x64 tiles; 8 rows x 4 cols/thread -> fma-bound, 256 CTAs)
    dim3 grid2(O / 64, B / 128);   // (4, 64) = 256 CTAs
    sgemm_nt_fused<1, 128, 64><<<grid2, block>>>(nullptr, w2, b2, out, B, O, H);

    (void)in_sizes; (void)n_in; (void)out_size;
}